// round 2
// baseline (speedup 1.0000x reference)
#include <cuda_runtime.h>
#include <stdint.h>

#define BATCH   16
#define NANCH   25200
#define NCLS    80
#define ROWLEN  85
#define KCAP    4096
#define MAXDET  300
#define CONF    0.45f
#define IOUT    0.45f
#define MAXWH   4096.0f
#define LISTCAP 512

// -------- device scratch (no allocations allowed) --------
__device__ int                g_count[BATCH];
__device__ unsigned long long g_keys[BATCH][KCAP];
__device__ int                g_n[BATCH];
__device__ float4             g_box[BATCH][KCAP];
__device__ float              g_score[BATCH][KCAP];
__device__ unsigned char      g_cls[BATCH][KCAP];
__device__ unsigned char      g_keep[BATCH][KCAP];

// -------- kernel 0: zero per-image counters --------
__global__ void init_kernel() {
    if (threadIdx.x < BATCH) g_count[threadIdx.x] = 0;
}

// -------- kernel 1: confidence filter --------
// One thread per anchor. obj <= CONF skips the class loop entirely (~95%).
// score = cls*obj <= obj, so score>CONF implies obj>CONF (reference's double
// condition collapses); we still gate on obj first for speed.
__global__ void filter_kernel(const float* __restrict__ pred) {
    int t = blockIdx.x * blockDim.x + threadIdx.x;
    if (t >= BATCH * NANCH) return;
    int img = t / NANCH;
    int a   = t - img * NANCH;
    const float* row = pred + (long long)t * ROWLEN;
    float obj = row[4];
    if (obj <= CONF) return;
#pragma unroll 4
    for (int c = 0; c < NCLS; c++) {
        float s = __fmul_rn(row[5 + c], obj);
        if (s > CONF) {
            unsigned int flat = (unsigned int)(a * NCLS + c);
            // sort key: descending score, then ascending flat index (jax top_k tie rule)
            unsigned long long key =
                ((unsigned long long)__float_as_uint(s) << 32) | (0xFFFFFFFFu - flat);
            int pos = atomicAdd(&g_count[img], 1);
            if (pos < KCAP) g_keys[img][pos] = key;
        }
    }
}

// -------- kernel 2: per-image bitonic sort of 4096 keys + materialize boxes --------
__global__ void sort_kernel(const float* __restrict__ pred) {
    __shared__ unsigned long long s[KCAP];   // 32 KB
    int img = blockIdx.x;
    int tid = threadIdx.x;                   // 1024 threads
    int cnt = g_count[img];
    int n   = cnt < KCAP ? cnt : KCAP;
    if (tid == 0) g_n[img] = n;

    // load inverted keys (padding ~0 -> sorts to end); sort ASCENDING on ~key
    for (int i = tid; i < KCAP; i += 1024)
        s[i] = (i < n) ? ~g_keys[img][i] : ~0ULL;
    __syncthreads();

    for (int k = 2; k <= KCAP; k <<= 1) {
        for (int j = k >> 1; j > 0; j >>= 1) {
#pragma unroll
            for (int rep = 0; rep < KCAP / 1024; rep++) {
                int i = tid + rep * 1024;
                int l = i ^ j;
                if (l > i) {
                    unsigned long long av = s[i], bv = s[l];
                    bool up = ((i & k) == 0);
                    if (up ? (av > bv) : (av < bv)) { s[i] = bv; s[l] = av; }
                }
            }
            __syncthreads();
        }
    }

    // write sorted candidate data
    for (int r = tid; r < KCAP; r += 1024) {
        g_keep[img][r] = 0;
        if (r < n) {
            unsigned long long key = ~s[r];
            float score = __uint_as_float((unsigned int)(key >> 32));
            unsigned int flat = 0xFFFFFFFFu - (unsigned int)(key & 0xFFFFFFFFu);
            int a = (int)(flat / NCLS);
            int c = (int)(flat - (unsigned int)a * NCLS);
            const float* row = pred + ((long long)img * NANCH + a) * ROWLEN;
            float x = row[0], y = row[1], w = row[2], h = row[3];
            float hw = __fmul_rn(w, 0.5f), hh = __fmul_rn(h, 0.5f);
            float4 bx;
            bx.x = __fsub_rn(x, hw);
            bx.y = __fsub_rn(y, hh);
            bx.z = __fadd_rn(x, hw);
            bx.w = __fadd_rn(y, hh);
            g_box[img][r]   = bx;
            g_score[img][r] = score;
            g_cls[img][r]   = (unsigned char)c;
        } else {
            g_box[img][r]   = make_float4(0.f, 0.f, 0.f, 0.f);
            g_score[img][r] = 0.f;
            g_cls[img][r]   = 255;
        }
    }
}

// -------- kernel 3: per-(image,class) greedy NMS, one warp each --------
// Class offsets (4096 per class) make cross-class IoU exactly 0, so greedy
// NMS decomposes per class. IoU is computed on offset coords to reproduce
// the reference's float rounding exactly.
__global__ void nms_kernel() {
    __shared__ unsigned short list[8][LISTCAP];
    int warp = threadIdx.x >> 5;
    int lane = threadIdx.x & 31;
    int task = blockIdx.x * 8 + warp;
    if (task >= BATCH * NCLS) return;
    int img = task / NCLS;
    int cls = task - img * NCLS;
    int n   = g_n[img];

    // collect this class's candidates in global score order
    int cnt = 0;
    for (int base = 0; base < KCAP; base += 32) {
        int idx = base + lane;
        bool m = (idx < n) && (g_cls[img][idx] == (unsigned char)cls);
        unsigned int bal = __ballot_sync(0xffffffffu, m);
        if (m) {
            int pos = cnt + __popc(bal & ((1u << lane) - 1u));
            if (pos < LISTCAP) list[warp][pos] = (unsigned short)idx;
        }
        cnt += __popc(bal);
        if (base + 32 >= n) break;
    }
    if (cnt > LISTCAP) cnt = LISTCAP;
    __syncwarp();

    float offs = __fmul_rn((float)cls, MAXWH);
    int kept = 0;
    for (int t = 0; t < cnt; t++) {
        int r = list[warp][t];
        float4 bb = g_box[img][r];
        float ax1 = __fadd_rn(bb.x, offs), ay1 = __fadd_rn(bb.y, offs);
        float ax2 = __fadd_rn(bb.z, offs), ay2 = __fadd_rn(bb.w, offs);
        float areaA = __fmul_rn(__fsub_rn(ax2, ax1), __fsub_rn(ay2, ay1));
        bool supp = false;
        for (int base = 0; base < kept && !supp; base += 32) {
            int i2 = base + lane;
            bool act = i2 < kept;
            int q = act ? list[warp][i2] : r;
            float4 kb = g_box[img][q];
            float bx1 = __fadd_rn(kb.x, offs), by1 = __fadd_rn(kb.y, offs);
            float bx2 = __fadd_rn(kb.z, offs), by2 = __fadd_rn(kb.w, offs);
            float ltx = fmaxf(ax1, bx1), lty = fmaxf(ay1, by1);
            float rbx = fminf(ax2, bx2), rby = fminf(ay2, by2);
            float iw = fmaxf(__fsub_rn(rbx, ltx), 0.f);
            float ih = fmaxf(__fsub_rn(rby, lty), 0.f);
            float inter = __fmul_rn(iw, ih);
            float areaB = __fmul_rn(__fsub_rn(bx2, bx1), __fsub_rn(by2, by1));
            float denom = __fadd_rn(__fsub_rn(__fadd_rn(areaA, areaB), inter), 1e-7f);
            float iou = __fdiv_rn(inter, denom);
            if (__any_sync(0xffffffffu, act && (iou > IOUT))) supp = true;
        }
        if (!supp) {
            if (lane == 0) {
                list[warp][kept] = (unsigned short)r;   // kept <= t, safe overwrite
                g_keep[img][r] = 1;
            }
            __syncwarp();
            kept++;
        }
    }
}

// -------- kernel 4: compact first 300 kept per image, write dets + mask --------
__global__ void output_kernel(float* __restrict__ out) {
    int img  = blockIdx.x;
    int tid  = threadIdx.x;          // 256
    int lane = tid & 31, warp = tid >> 5;
    __shared__ int wsums[8];
    __shared__ int s_off;

    float* dets = out;                           // [B][300][6]
    float* mask = out + BATCH * MAXDET * 6;      // [B][300]

    for (int j = tid; j < MAXDET * 6; j += 256)
        dets[img * MAXDET * 6 + j] = 0.f;
    if (tid == 0) s_off = 0;
    __syncthreads();

    for (int base = 0; base < KCAP; base += 256) {
        int idx = base + tid;
        int f = g_keep[img][idx];
        unsigned int bal = __ballot_sync(0xffffffffu, f);
        int prefix = __popc(bal & ((1u << lane) - 1u));
        if (lane == 0) wsums[warp] = __popc(bal);
        __syncthreads();
        int woff = 0;
        for (int w = 0; w < warp; w++) woff += wsums[w];
        int rank = s_off + woff + prefix;
        if (f && rank < MAXDET) {
            float4 bb = g_box[img][idx];
            float* d = dets + ((long long)img * MAXDET + rank) * 6;
            d[0] = bb.x; d[1] = bb.y; d[2] = bb.z; d[3] = bb.w;
            d[4] = g_score[img][idx];
            d[5] = (float)g_cls[img][idx];
        }
        __syncthreads();
        if (tid == 0) {
            int tot = 0;
            for (int w = 0; w < 8; w++) tot += wsums[w];
            s_off += tot;
        }
        __syncthreads();
    }

    int nk = s_off < MAXDET ? s_off : MAXDET;
    for (int j = tid; j < MAXDET; j += 256)
        mask[img * MAXDET + j] = (j < nk) ? 1.0f : 0.0f;
}

extern "C" void kernel_launch(void* const* d_in, const int* in_sizes, int n_in,
                              void* d_out, int out_size) {
    const float* pred = (const float*)d_in[0];
    float* out = (float*)d_out;
    (void)in_sizes; (void)n_in; (void)out_size;

    init_kernel<<<1, 32>>>();
    filter_kernel<<<(BATCH * NANCH + 255) / 256, 256>>>(pred);
    sort_kernel<<<BATCH, 1024>>>(pred);
    nms_kernel<<<(BATCH * NCLS + 7) / 8, 256>>>();
    output_kernel<<<BATCH, 256>>>(out);
}

// round 3
// speedup vs baseline: 1.3176x; 1.3176x over previous
#include <cuda_runtime.h>
#include <stdint.h>

#define BATCH   16
#define NANCH   25200
#define NCLS    80
#define ROWLEN  85
#define KCAP    4096
#define MAXDET  300
#define CONF    0.45f
#define IOUT    0.45f
#define MAXWH   4096.0f
#define CLSCAP  256     // per-class candidate cap (avg ~30, huge safety margin)

// -------- device scratch (no allocations allowed) --------
__device__ int                g_count[BATCH];
__device__ unsigned long long g_keys[BATCH][KCAP];
__device__ float4             g_box[BATCH][KCAP];
__device__ float              g_score[BATCH][KCAP];
__device__ unsigned char     g_cls[BATCH][KCAP];
__device__ unsigned char     g_keep[BATCH][KCAP];
__device__ unsigned short    g_list[BATCH][KCAP];   // class-grouped sorted-rank indices
__device__ int                g_clsOff[BATCH][NCLS + 1];

// -------- kernel 0: zero per-image counters --------
__global__ void init_kernel() {
    if (threadIdx.x < BATCH) g_count[threadIdx.x] = 0;
}

// -------- kernel 1: confidence filter --------
__global__ void filter_kernel(const float* __restrict__ pred) {
    int t = blockIdx.x * blockDim.x + threadIdx.x;
    if (t >= BATCH * NANCH) return;
    int img = t / NANCH;
    int a   = t - img * NANCH;
    const float* row = pred + (long long)t * ROWLEN;
    float obj = row[4];
    if (obj <= CONF) return;      // score = cls*obj <= obj, so obj gate is exact
#pragma unroll 4
    for (int c = 0; c < NCLS; c++) {
        float s = __fmul_rn(row[5 + c], obj);
        if (s > CONF) {
            unsigned int flat = (unsigned int)(a * NCLS + c);
            // descending score, then ascending flat index (jax top_k tie rule)
            unsigned long long key =
                ((unsigned long long)__float_as_uint(s) << 32) | (0xFFFFFFFFu - flat);
            int pos = atomicAdd(&g_count[img], 1);
            if (pos < KCAP) g_keys[img][pos] = key;
        }
    }
}

// ---- bitonic helpers (sorting ASCENDING on inverted keys) ----
__device__ __forceinline__ void cswap(unsigned long long& a, unsigned long long& b, bool dir) {
    // a sits at the lower index; ascending order iff dir
    if ((a > b) == dir) { unsigned long long t = a; a = b; b = t; }
}

// All phases of stage k with j <= 64, executed in registers.
// Thread holds elements idx_m = base + lane + 32*m, m = 0..3 (warp owns 128 elems).
__device__ __forceinline__ void local_stage(unsigned long long v[4], int base, int lane, int k) {
    if (k >= 128) {                       // j = 64 phase
        bool d0 = (((base + lane)      & k) == 0);
        bool d1 = (((base + lane + 32) & k) == 0);
        cswap(v[0], v[2], d0);
        cswap(v[1], v[3], d1);
    }
    if (k >= 64) {                        // j = 32 phase
        bool d0 = (((base + lane)      & k) == 0);
        bool d1 = (((base + lane + 64) & k) == 0);
        cswap(v[0], v[1], d0);
        cswap(v[2], v[3], d1);
    }
    int jstart = (k >> 1) < 16 ? (k >> 1) : 16;
    for (int j = jstart; j >= 1; j >>= 1) {
#pragma unroll
        for (int m = 0; m < 4; m++) {
            int idx = base + lane + 32 * m;
            unsigned long long other = __shfl_xor_sync(0xffffffffu, v[m], j);
            bool lower = ((idx & j) == 0);
            bool dir   = ((idx & k) == 0);
            bool keepmin = (lower == dir);
            v[m] = keepmin ? (v[m] < other ? v[m] : other)
                           : (v[m] > other ? v[m] : other);
        }
    }
}

// -------- kernel 2: per-image register-staged bitonic sort + class grouping --------
__global__ void sort_kernel(const float* __restrict__ pred) {
    __shared__ unsigned long long s[KCAP];        // 32 KB
    __shared__ int hist[NCLS], start[NCLS + 1], hist2[NCLS];
    int img  = blockIdx.x;
    int tid  = threadIdx.x;                       // 1024 threads
    int lane = tid & 31;
    int base = (tid >> 5) * 128;                  // warp-owned region
    int cnt  = g_count[img];
    int n    = cnt < KCAP ? cnt : KCAP;
    if (tid < NCLS) { hist[tid] = 0; hist2[tid] = 0; }

    unsigned long long v[4];
#pragma unroll
    for (int m = 0; m < 4; m++) {
        int idx = base + lane + 32 * m;
        v[m] = (idx < n) ? ~g_keys[img][idx] : ~0ULL;   // pads sort to end
    }

    // fully warp-local stages k = 2..64
    for (int k = 2; k <= 64; k <<= 1) local_stage(v, base, lane, k);

#pragma unroll
    for (int m = 0; m < 4; m++) s[base + lane + 32 * m] = v[m];
    __syncthreads();

    // stages k = 128..4096: cross-warp phases (j >= 128) in smem, tail in regs
    for (int k = 128; k <= KCAP; k <<= 1) {
        for (int j = k >> 1; j >= 128; j >>= 1) {
            for (int t2 = tid; t2 < KCAP / 2; t2 += 1024) {
                int i = ((t2 & ~(j - 1)) << 1) | (t2 & (j - 1));
                int l = i | j;
                unsigned long long a = s[i], b = s[l];
                bool dir = ((i & k) == 0);
                if ((a > b) == dir) { s[i] = b; s[l] = a; }
            }
            __syncthreads();
        }
#pragma unroll
        for (int m = 0; m < 4; m++) v[m] = s[base + lane + 32 * m];
        local_stage(v, base, lane, k);
        if (k < KCAP) {
#pragma unroll
            for (int m = 0; m < 4; m++) s[base + lane + 32 * m] = v[m];
            __syncthreads();
        }
    }

    // epilogue: decode from registers, materialize boxes, histogram classes
    int carr[4];
#pragma unroll
    for (int m = 0; m < 4; m++) {
        int r = base + lane + 32 * m;             // sorted rank
        g_keep[img][r] = 0;
        if (r < n) {
            unsigned long long key = ~v[m];
            float score = __uint_as_float((unsigned int)(key >> 32));
            unsigned int flat = 0xFFFFFFFFu - (unsigned int)(key & 0xFFFFFFFFu);
            int a = (int)(flat / NCLS);
            int c = (int)(flat - (unsigned int)a * NCLS);
            const float* row = pred + ((long long)img * NANCH + a) * ROWLEN;
            float x = row[0], y = row[1], w = row[2], h = row[3];
            float hw = __fmul_rn(w, 0.5f), hh = __fmul_rn(h, 0.5f);
            float4 bx;
            bx.x = __fsub_rn(x, hw);
            bx.y = __fsub_rn(y, hh);
            bx.z = __fadd_rn(x, hw);
            bx.w = __fadd_rn(y, hh);
            g_box[img][r]   = bx;
            g_score[img][r] = score;
            g_cls[img][r]   = (unsigned char)c;
            carr[m] = c;
            atomicAdd(&hist[c], 1);
        } else {
            g_box[img][r]   = make_float4(0.f, 0.f, 0.f, 0.f);
            g_score[img][r] = 0.f;
            g_cls[img][r]   = 255;
            carr[m] = -1;
        }
    }
    __syncthreads();
    if (tid == 0) {
        int acc = 0;
        for (int c = 0; c < NCLS; c++) { start[c] = acc; acc += hist[c]; }
        start[NCLS] = acc;
    }
    __syncthreads();
    if (tid <= NCLS) g_clsOff[img][tid] = start[tid];
    // scatter sorted-rank indices into class segments (unordered within class)
#pragma unroll
    for (int m = 0; m < 4; m++) {
        if (carr[m] >= 0) {
            int c   = carr[m];
            int pos = start[c] + atomicAdd(&hist2[c], 1);
            g_list[img][pos] = (unsigned short)(base + lane + 32 * m);
        }
    }
}

// -------- kernel 3: per-(image,class) greedy NMS, one warp each --------
// Processes candidates in score order by extracting min sorted-rank each step.
// Kept (offset) boxes cached in shared memory -> zero global loads in inner loop.
__global__ void nms_kernel() {
    __shared__ float4 kb_s[8][CLSCAP];            // 32 KB
    int warp = threadIdx.x >> 5;
    int lane = threadIdx.x & 31;
    int task = blockIdx.x * 8 + warp;
    if (task >= BATCH * NCLS) return;
    int img = task / NCLS;
    int cls = task - img * NCLS;
    int st  = g_clsOff[img][cls];
    int cnt = g_clsOff[img][cls + 1] - st;
    if (cnt <= 0) return;
    if (cnt > CLSCAP) cnt = CLSCAP;

    unsigned rl[8];
#pragma unroll
    for (int m = 0; m < 8; m++) {
        int p = lane + 32 * m;
        rl[m] = (p < cnt) ? (unsigned)g_list[img][st + p] : 0xFFFFu;
    }

    float offs = __fmul_rn((float)cls, MAXWH);
    int kept = 0;
    for (int it = 0; it < cnt; it++) {
        unsigned mn = 0xFFFFu;
#pragma unroll
        for (int m = 0; m < 8; m++) mn = mn < rl[m] ? mn : rl[m];
#pragma unroll
        for (int o = 16; o >= 1; o >>= 1) {
            unsigned x = __shfl_xor_sync(0xffffffffu, mn, o);
            mn = mn < x ? mn : x;
        }
        unsigned r = mn;                          // next-best score in this class
#pragma unroll
        for (int m = 0; m < 8; m++) if (rl[m] == r) rl[m] = 0xFFFFu;

        float4 bb = g_box[img][r];
        float ax1 = __fadd_rn(bb.x, offs), ay1 = __fadd_rn(bb.y, offs);
        float ax2 = __fadd_rn(bb.z, offs), ay2 = __fadd_rn(bb.w, offs);
        float areaA = __fmul_rn(__fsub_rn(ax2, ax1), __fsub_rn(ay2, ay1));
        bool supp = false;
        for (int b2 = 0; b2 < kept && !supp; b2 += 32) {
            int i2 = b2 + lane;
            bool act = i2 < kept;
            float4 kb = kb_s[warp][act ? i2 : 0];
            float ltx = fmaxf(ax1, kb.x), lty = fmaxf(ay1, kb.y);
            float rbx = fminf(ax2, kb.z), rby = fminf(ay2, kb.w);
            float iw = fmaxf(__fsub_rn(rbx, ltx), 0.f);
            float ih = fmaxf(__fsub_rn(rby, lty), 0.f);
            float inter = __fmul_rn(iw, ih);
            float areaB = __fmul_rn(__fsub_rn(kb.z, kb.x), __fsub_rn(kb.w, kb.y));
            float denom = __fadd_rn(__fsub_rn(__fadd_rn(areaA, areaB), inter), 1e-7f);
            float iou = __fdiv_rn(inter, denom);
            if (__any_sync(0xffffffffu, act && (iou > IOUT))) supp = true;
        }
        if (!supp) {
            if (lane == 0) {
                kb_s[warp][kept] = make_float4(ax1, ay1, ax2, ay2);
                g_keep[img][r] = 1;
            }
            __syncwarp();
            kept++;
        }
    }
}

// -------- kernel 4: compact first 300 kept per image, write dets + mask --------
__global__ void output_kernel(float* __restrict__ out) {
    int img  = blockIdx.x;
    int tid  = threadIdx.x;          // 256
    int lane = tid & 31, warp = tid >> 5;
    __shared__ int wsums[8];
    __shared__ int s_off;

    float* dets = out;                           // [B][300][6]
    float* mask = out + BATCH * MAXDET * 6;      // [B][300]

    for (int j = tid; j < MAXDET * 6; j += 256)
        dets[img * MAXDET * 6 + j] = 0.f;
    if (tid == 0) s_off = 0;
    __syncthreads();

    for (int base = 0; base < KCAP; base += 256) {
        int idx = base + tid;
        int f = g_keep[img][idx];
        unsigned int bal = __ballot_sync(0xffffffffu, f);
        int prefix = __popc(bal & ((1u << lane) - 1u));
        if (lane == 0) wsums[warp] = __popc(bal);
        __syncthreads();
        int woff = 0;
        for (int w = 0; w < warp; w++) woff += wsums[w];
        int rank = s_off + woff + prefix;
        if (f && rank < MAXDET) {
            float4 bb = g_box[img][idx];
            float* d = dets + ((long long)img * MAXDET + rank) * 6;
            d[0] = bb.x; d[1] = bb.y; d[2] = bb.z; d[3] = bb.w;
            d[4] = g_score[img][idx];
            d[5] = (float)g_cls[img][idx];
        }
        __syncthreads();
        if (tid == 0) {
            int tot = 0;
            for (int w = 0; w < 8; w++) tot += wsums[w];
            s_off += tot;
        }
        __syncthreads();
    }

    int nk = s_off < MAXDET ? s_off : MAXDET;
    for (int j = tid; j < MAXDET; j += 256)
        mask[img * MAXDET + j] = (j < nk) ? 1.0f : 0.0f;
}

extern "C" void kernel_launch(void* const* d_in, const int* in_sizes, int n_in,
                              void* d_out, int out_size) {
    const float* pred = (const float*)d_in[0];
    float* out = (float*)d_out;
    (void)in_sizes; (void)n_in; (void)out_size;

    init_kernel<<<1, 32>>>();
    filter_kernel<<<(BATCH * NANCH + 255) / 256, 256>>>(pred);
    sort_kernel<<<BATCH, 1024>>>(pred);
    nms_kernel<<<(BATCH * NCLS + 7) / 8, 256>>>();
    output_kernel<<<BATCH, 256>>>(out);
}